// round 14
// baseline (speedup 1.0000x reference)
#include <cuda_runtime.h>

// Problem constants
#define NN 32
#define CC 64
#define TTT 256
#define VV 25
#define RR 8
#define OO 64
#define SS 3
#define STREAM_ELEMS (NN*OO*TTT*VV)   // 13,107,200
#define NTV (NN*TTT*VV)               // 204,800
#define AROW 704                      // per-o a block: 25 u-rows * 28 + pad

typedef unsigned long long u64;

__device__ __forceinline__ u64 pack2(float lo, float hi) {
    u64 r; asm("mov.b64 %0,{%1,%2};" : "=l"(r) : "f"(lo), "f"(hi)); return r;
}
__device__ __forceinline__ void unpack2(u64 p, float& lo, float& hi) {
    asm("mov.b64 {%0,%1},%2;" : "=f"(lo), "=f"(hi) : "l"(p));
}
__device__ __forceinline__ void ffma2(u64& d, u64 a, u64 b) {
    asm("fma.rn.f32x2 %0,%1,%2,%0;" : "+l"(d) : "l"(a), "l"(b));
}
__device__ __forceinline__ unsigned to_tf32(float f) {
    unsigned r; asm("cvt.rna.tf32.f32 %0, %1;" : "=r"(r) : "f"(f)); return r;
}
__device__ __forceinline__ void mma_tf32(float& d0, float& d1, float& d2, float& d3,
                                         unsigned a0, unsigned a1, unsigned a2, unsigned a3,
                                         unsigned b0, unsigned b1) {
    asm volatile(
        "mma.sync.aligned.m16n8k8.row.col.f32.tf32.tf32.f32 "
        "{%0,%1,%2,%3},{%4,%5,%6,%7},{%8,%9},{%0,%1,%2,%3};\n"
        : "+f"(d0), "+f"(d1), "+f"(d2), "+f"(d3)
        : "r"(a0), "r"(a1), "r"(a2), "r"(a3), "r"(b0), "r"(b1));
}

// ---------------- scratch (zero-initialized; a pad positions never written) ---
__device__ float g_xm[2][NN][CC][VV];
__device__ float g_r[2][SS][NN][RR][VV];
__device__ float g_a[2][SS][NN][OO][AROW];          // ~34.6 MB, pitch-28 u-rows
__device__ float g_sum[2][OO];
__device__ float g_sumsq[2][OO];
__device__ float g_mean[2][OO];
__device__ float g_rstd[2][OO];

// ---------------- K1: mean over T (+ zero stats in block 0) ------------------
__global__ void k_mean(const float* __restrict__ x1, const float* __restrict__ x2) {
    int b   = blockIdx.x;
    int tid = threadIdx.x;
    if (b == 0 && tid < 2*OO) {
        ((float*)g_sum)[tid]   = 0.f;
        ((float*)g_sumsq)[tid] = 0.f;
    }
    int s   = b / (NN*CC);
    int rem = b % (NN*CC);
    const float* x = s ? x2 : x1;
    const float* p = x + (size_t)rem * TTT * VV;
    float acc = 0.f;
    #pragma unroll
    for (int k = 0; k < 8; k++) acc += p[tid + k*800];
    __shared__ float part[800];
    part[tid] = acc;
    __syncthreads();
    if (tid < VV) {
        float sum = 0.f;
        #pragma unroll
        for (int tg = 0; tg < 32; tg++) sum += part[tg*VV + tid];
        g_xm[s][rem/CC][rem%CC][tid] = sum * (1.0f/TTT);
    }
}

// ---------------- K2: r = w·xm + b ------------------------------------------
__global__ void k_r(const float* __restrict__ c1w, const float* __restrict__ c1b,
                    const float* __restrict__ c2w, const float* __restrict__ c2b) {
    int i = blockIdx.x / NN, n = blockIdx.x % NN;
    int tid = threadIdx.x;
    if (tid >= 2*RR*VV) return;
    int s  = tid / (RR*VV);
    int rv = tid % (RR*VV);
    int r  = rv / VV, v = rv % VV;
    const float* w  = s ? c2w : c1w;
    const float* bb = s ? c2b : c1b;
    const float* wrow = w + (i*RR + r)*CC;
    const float* xm   = &g_xm[s][n][0][v];
    float acc = bb[i*RR + r];
    #pragma unroll 8
    for (int c = 0; c < CC; c++) acc += wrow[c] * xm[c*VV];
    g_r[s][i][n][r][v] = acc;
}

// ---------------- K3: rel=tanh(r1-r2); a1,a2 -> pitch-28 g_a -----------------
__global__ void k_a(const float* __restrict__ PA, const float* __restrict__ alpha,
                    const float* __restrict__ c5w, const float* __restrict__ c5b,
                    const float* __restrict__ c6w, const float* __restrict__ c6b) {
    int bx = blockIdx.x;                 // o-quarter
    int i  = blockIdx.y / NN, n = blockIdx.y % NN;
    __shared__ float rel[RR][VV*VV];
    __shared__ float r1s[RR][VV], r2s[RR][VV];
    __shared__ u64  wp_s[16*RR];
    int tid = threadIdx.x;
    if (tid < RR*VV) {
        int r = tid/VV, v = tid%VV;
        r1s[r][v] = g_r[0][i][n][r][v];
        r2s[r][v] = g_r[1][i][n][r][v];
    }
    if (tid < 16*RR) {
        int o = tid / RR, r = tid % RR;
        int idx = (i*OO + bx*16 + o)*RR + r;
        wp_s[tid] = pack2(c5w[idx], c6w[idx]);
    }
    __syncthreads();
    {
        int r = 0, uv = tid;
        int u = uv / VV, v = uv - u*VV;
        while (r < RR) {
            rel[r][uv] = tanhf(r1s[r][u] - r2s[r][v]);
            uv += 256;
            if (uv >= VV*VV) { uv -= VV*VV; r++; }
            u = uv / VV; v = uv - u*VV;
        }
    }
    __syncthreads();
    float al = alpha[0];
    {
        int ol = 0, uv = tid;
        while (ol < 16) {
            int o = bx*16 + ol;
            int u = uv / VV, v = uv - u*VV;
            float a1 = c5b[i*OO + o] + PA[i*VV*VV + uv];
            float a2 = c6b[i*OO + o] + al;
            u64 acc = pack2(a1, a2);
            #pragma unroll
            for (int r = 0; r < RR; r++) {
                float rv = rel[r][uv];
                ffma2(acc, wp_s[ol*RR + r], pack2(rv, rv));
            }
            float lo, hi; unpack2(acc, lo, hi);
            g_a[0][i][n][o][u*28 + v] = lo;
            g_a[1][i][n][o][u*28 + v] = hi;
            uv += 256;
            if (uv >= VV*VV) { uv -= VV*VV; ol++; }
        }
    }
}

// ---------------- K_FUSE: mma conv + graph contraction, no global x3 ---------
// Grid (8 o-groups, NN, 8 = 2s x 4 T-quarters). Block 512 = 16 warps.
// Per chunk (400 tv = 16 t): stage X tf32 -> [mma(i) -> x3s smem; phase-2(i)]x3
// -> coalesced y store. a-slices (3 subsets x 8 o) resident for whole block.
// smem (floats): as_ 24x704 (67584B) | xs 64x408 (104448B) | x3s 8x448 (14336B)
#define FS_AS   0
#define FS_XS   (24*704)
#define FS_X3S  (24*704 + 64*408)
#define FUSE_SMEM ((24*704 + 64*408 + 8*448)*4)   // 186368

__global__ void __launch_bounds__(512, 1)
k_fuse(const float* __restrict__ x1, const float* __restrict__ x2,
       const float* __restrict__ c3w, const float* __restrict__ c3b,
       const float* __restrict__ c4w, const float* __restrict__ c4b,
       float* __restrict__ out) {
    extern __shared__ __align__(16) float fs[];
    float*    as_ = fs + FS_AS;          // [24][704]  (i*8 + o_local)
    unsigned* xs  = (unsigned*)(fs + FS_XS);   // [64][408] tf32 bits
    float*    x3s = fs + FS_X3S;         // [8][448] (t*28+v rows); reused for y

    int obase = blockIdx.x * 8;
    int n     = blockIdx.y;
    int z     = blockIdx.z;
    int s     = z >> 2;
    int cq    = z & 3;                   // T-quarter: chunks cq*4 .. cq*4+3
    const float* x  = s ? x2  : x1;
    const float* cw = s ? c4w : c3w;
    const float* cb = s ? c4b : c3b;
    float* yout = out + (size_t)s * STREAM_ELEMS;

    int tid  = threadIdx.x;
    int wid  = tid >> 5, lane = tid & 31;
    int tig  = lane & 3, grp = lane >> 2;
    int oc   = 2*tig;                    // mma D column pair (local o)

    // phase-2 mapping: warp -> (o_local, t-half); lane -> (t, u-group)
    int o_l = wid & 7;
    int th  = wid >> 3;
    int tl  = th*8 + (lane & 7);         // local t 0..15
    int ug  = lane >> 3;                 // u-group 0..3
    int u0  = (ug == 0) ? 0 : 7 + (ug-1)*6;
    int ucnt= (ug == 0) ? 7 : 6;         // 7+6+6+6 = 25

    // ---- stage a (3 subsets x 8 o, pitch 704) once
    for (int q = tid; q < 24*176; q += 512) {
        int io = q / 176, j4 = q - io*176;
        int i  = io >> 3, ol = io & 7;
        ((float4*)as_)[io*176 + j4] =
            ((const float4*)&g_a[s][i][n][obase + ol][0])[j4];
    }
    // ---- zero x3s once (pads must be finite: a-pads are 0, 0*NaN != 0)
    for (int q = tid; q < 8*448/4; q += 512)
        ((float4*)x3s)[q] = make_float4(0.f, 0.f, 0.f, 0.f);

    float ls = 0.f, lq = 0.f;            // running channel stats
    __syncthreads();

    for (int cc = 0; cc < 4; cc++) {
        int base = (cq*4 + cc) * 400;    // tv chunk base (16 t)

        // ---- stage X chunk as tf32 bits
        for (int p4 = tid; p4 < 6400; p4 += 512) {
            int c = p4 / 100, pos = (p4 - c*100) * 4;
            float4 v = *(const float4*)(x + ((size_t)(n*CC + c))*TTT*VV + base + pos);
            uint4 u;
            u.x = to_tf32(v.x); u.y = to_tf32(v.y);
            u.z = to_tf32(v.z); u.w = to_tf32(v.w);
            *(uint4*)&xs[c*408 + pos] = u;
        }
        __syncthreads();

        float yacc[7];
        #pragma unroll
        for (int k = 0; k < 7; k++) yacc[k] = 0.f;

        for (int i = 0; i < SS; i++) {
            // ---- mma: x3[o8][400tv] from xs, 25 m-tiles over 16 warps
            {
                unsigned B0[8], B1[8];
                #pragma unroll
                for (int k = 0; k < 8; k++) {
                    B0[k] = to_tf32(cw[(i*OO + obase + grp)*CC + k*8 + tig]);
                    B1[k] = to_tf32(cw[(i*OO + obase + grp)*CC + k*8 + tig + 4]);
                }
                float blo = cb[i*OO + obase + oc];
                float bhi = cb[i*OO + obase + oc + 1];

                for (int mt = wid; mt < 25; mt += 16) {
                    int m0 = mt * 16;
                    float d0 = blo, d1 = bhi, d2 = blo, d3 = bhi;
                    #pragma unroll
                    for (int k = 0; k < 8; k++) {
                        unsigned a0 = xs[(k*8 + tig    )*408 + m0 +     grp];
                        unsigned a1 = xs[(k*8 + tig    )*408 + m0 + 8 + grp];
                        unsigned a2 = xs[(k*8 + tig + 4)*408 + m0 +     grp];
                        unsigned a3 = xs[(k*8 + tig + 4)*408 + m0 + 8 + grp];
                        mma_tf32(d0, d1, d2, d3, a0, a1, a2, a3, B0[k], B1[k]);
                    }
                    int tv0 = m0 + grp;
                    int t0 = (tv0 * 5243) >> 17; int off0 = t0*28 + (tv0 - t0*25);
                    int tv1 = tv0 + 8;
                    int t1 = (tv1 * 5243) >> 17; int off1 = t1*28 + (tv1 - t1*25);
                    x3s[ oc     *448 + off0] = d0;
                    x3s[(oc + 1)*448 + off0] = d1;
                    x3s[ oc     *448 + off1] = d2;
                    x3s[(oc + 1)*448 + off1] = d3;
                }
            }
            __syncthreads();

            // ---- phase-2: yacc[u] += sum_v a[i][o_l][u][v] * x3[o_l][tl][v]
            {
                u64 xp[14];
                const ulonglong2* xr2 = (const ulonglong2*)&x3s[o_l*448 + tl*28];
                #pragma unroll
                for (int j = 0; j < 7; j++) {
                    ulonglong2 t = xr2[j];
                    xp[2*j] = t.x; xp[2*j+1] = t.y;
                }
                const float* ga = &as_[(i*8 + o_l)*704];
                #pragma unroll
                for (int k = 0; k < 7; k++) {
                    if (k >= ucnt) break;
                    const ulonglong2* ar2 = (const ulonglong2*)(ga + (u0 + k)*28);
                    u64 accA = 0ull, accB = 0ull;
                    #pragma unroll
                    for (int j = 0; j < 7; j++) {
                        ulonglong2 av = ar2[j];
                        ffma2(accA, av.x, xp[2*j]);
                        ffma2(accB, av.y, xp[2*j+1]);
                    }
                    float a0, a1, b0, b1;
                    unpack2(accA, a0, a1); unpack2(accB, b0, b1);
                    yacc[k] += (a0 + a1) + (b0 + b1);
                }
            }
            __syncthreads();   // before next subset's mma overwrites x3s
        }

        // ---- stats from registers
        #pragma unroll
        for (int k = 0; k < 7; k++) {
            if (k >= ucnt) break;
            ls += yacc[k]; lq += yacc[k]*yacc[k];
        }

        // ---- stage y compactly into x3s region, then coalesced store
        #pragma unroll
        for (int k = 0; k < 7; k++) {
            if (k >= ucnt) break;
            x3s[o_l*400 + tl*25 + u0 + k] = yacc[k];
        }
        __syncthreads();
        for (int q = tid; q < 800; q += 512) {
            int ol = q / 100, pos = (q - ol*100) * 4;
            float4 v = *(float4*)&x3s[ol*400 + pos];
            *(float4*)(yout + (size_t)(n*OO + obase + ol)*TTT*VV + base + pos) = v;
        }
        __syncthreads();   // y reads done before next chunk's mma writes x3s
    }

    // ---- warp-reduce stats, one atomic per warp (2 warps per o)
    #pragma unroll
    for (int off = 16; off; off >>= 1) {
        ls += __shfl_down_sync(0xffffffffu, ls, off);
        lq += __shfl_down_sync(0xffffffffu, lq, off);
    }
    if (lane == 0) {
        atomicAdd(&g_sum[s][obase + o_l],   ls);
        atomicAdd(&g_sumsq[s][obase + o_l], lq);
    }
}

// ---------------- K5 ---------------------------------------------------------
__global__ void k_stats() {
    int i = threadIdx.x;
    if (i < 2*OO) {
        int s = i / OO, o = i % OO;
        float m = g_sum[s][o] * (1.0f/NTV);
        float v = g_sumsq[s][o] * (1.0f/NTV) - m*m;
        g_mean[s][o] = m;
        g_rstd[s][o] = rsqrtf(v + 1e-5f);
    }
}

// ---------------- K6: BN + residual + ReLU -----------------------------------
__global__ void k_bn(const float* __restrict__ x1, const float* __restrict__ x2,
                     const float* __restrict__ bn1w, const float* __restrict__ bn1b,
                     const float* __restrict__ bn2w, const float* __restrict__ bn2b,
                     float* __restrict__ out) {
    const long total4 = 2L * STREAM_ELEMS / 4;
    long stride = (long)gridDim.x * blockDim.x;
    for (long q = (long)blockIdx.x * blockDim.x + threadIdx.x; q < total4; q += stride) {
        long e   = q * 4;
        int  s   = (int)(e / STREAM_ELEMS);
        long rem = e % STREAM_ELEMS;
        int  o   = (int)((rem / (TTT*VV)) % OO);
        const float* bw = s ? bn2w : bn1w;
        const float* bb = s ? bn2b : bn1b;
        const float* xr = s ? x2   : x1;
        float m  = g_mean[s][o], rs = g_rstd[s][o];
        float sc = rs * bw[o];
        float sh = bb[o] - m * sc;
        float4 yv = ((float4*)out)[q];
        float4 xv = ((const float4*)xr)[rem/4];
        yv.x = fmaxf(fmaf(yv.x, sc, sh) + xv.x, 0.f);
        yv.y = fmaxf(fmaf(yv.y, sc, sh) + xv.y, 0.f);
        yv.z = fmaxf(fmaf(yv.z, sc, sh) + xv.z, 0.f);
        yv.w = fmaxf(fmaf(yv.w, sc, sh) + xv.w, 0.f);
        ((float4*)out)[q] = yv;
    }
}

// ---------------- launcher ---------------------------------------------------
extern "C" void kernel_launch(void* const* d_in, const int* in_sizes, int n_in,
                              void* d_out, int out_size) {
    const float* x1    = (const float*)d_in[0];
    const float* x2    = (const float*)d_in[1];
    const float* PA    = (const float*)d_in[2];
    const float* alpha = (const float*)d_in[3];
    const float* c1w   = (const float*)d_in[4];
    const float* c1b   = (const float*)d_in[5];
    const float* c2w   = (const float*)d_in[6];
    const float* c2b   = (const float*)d_in[7];
    const float* c3w   = (const float*)d_in[8];
    const float* c3b   = (const float*)d_in[9];
    const float* c4w   = (const float*)d_in[10];
    const float* c4b   = (const float*)d_in[11];
    const float* c5w   = (const float*)d_in[12];
    const float* c5b   = (const float*)d_in[13];
    const float* c6w   = (const float*)d_in[14];
    const float* c6b   = (const float*)d_in[15];
    const float* bn1w  = (const float*)d_in[16];
    const float* bn1b  = (const float*)d_in[17];
    const float* bn2w  = (const float*)d_in[18];
    const float* bn2b  = (const float*)d_in[19];
    float* out = (float*)d_out;

    cudaFuncSetAttribute(k_fuse, cudaFuncAttributeMaxDynamicSharedMemorySize, FUSE_SMEM);

    k_mean<<<2*NN*CC, 800>>>(x1, x2);
    k_r<<<SS*NN, 512>>>(c1w, c1b, c2w, c2b);
    k_a<<<dim3(4, SS*NN), 256>>>(PA, alpha, c5w, c5b, c6w, c6b);
    k_fuse<<<dim3(8, NN, 8), 512, FUSE_SMEM>>>(x1, x2, c3w, c3b, c4w, c4b, out);
    k_stats<<<1, 128>>>();
    k_bn<<<8192, 256>>>(x1, x2, bn1w, bn1b, bn2w, bn2b, out);
}

// round 15
// speedup vs baseline: 1.7747x; 1.7747x over previous
#include <cuda_runtime.h>
#include <cuda_fp16.h>

// Problem constants
#define NN 32
#define CC 64
#define TTT 256
#define VV 25
#define RR 8
#define OO 64
#define SS 3
#define STREAM_ELEMS (NN*OO*TTT*VV)   // 13,107,200
#define NTV (NN*TTT*VV)               // 204,800
#define AROW 652                      // padded a-row per o (16B-mult, pitch-26)
#define X3ROW 6656                    // padded x3 row per o: 256 t * 26 (halves)

typedef unsigned long long u64;

__device__ __forceinline__ u64 pack2(float lo, float hi) {
    u64 r; asm("mov.b64 %0,{%1,%2};" : "=l"(r) : "f"(lo), "f"(hi)); return r;
}
__device__ __forceinline__ void unpack2(u64 p, float& lo, float& hi) {
    asm("mov.b64 {%0,%1},%2;" : "=f"(lo), "=f"(hi) : "l"(p));
}
__device__ __forceinline__ void ffma2(u64& d, u64 a, u64 b) {
    asm("fma.rn.f32x2 %0,%1,%2,%0;" : "+l"(d) : "l"(a), "l"(b));
}
__device__ __forceinline__ unsigned to_tf32(float f) {
    unsigned r; asm("cvt.rna.tf32.f32 %0, %1;" : "=r"(r) : "f"(f)); return r;
}
__device__ __forceinline__ void mma_tf32(float& d0, float& d1, float& d2, float& d3,
                                         unsigned a0, unsigned a1, unsigned a2, unsigned a3,
                                         unsigned b0, unsigned b1) {
    asm volatile(
        "mma.sync.aligned.m16n8k8.row.col.f32.tf32.tf32.f32 "
        "{%0,%1,%2,%3},{%4,%5,%6,%7},{%8,%9},{%0,%1,%2,%3};\n"
        : "+f"(d0), "+f"(d1), "+f"(d2), "+f"(d3)
        : "r"(a0), "r"(a1), "r"(a2), "r"(a3), "r"(b0), "r"(b1));
}

// ---------------- scratch ----------------------------------------------------
__device__ float  g_xm[2][NN][CC][VV];
__device__ float  g_r[2][SS][NN][RR][VV];
__device__ float  g_a[2][SS][NN][OO][AROW];         // ~32 MB, pitch-26 u-rows
__device__ __half g_x3h[2][SS][NN][OO][X3ROW];      // ~163 MB fp16 conv output
__device__ float  g_sum[2][OO];
__device__ float  g_sumsq[2][OO];
__device__ float  g_mean[2][OO];
__device__ float  g_rstd[2][OO];

// ---------------- K1: mean over T (+ zero stats in block 0) ------------------
__global__ void k_mean(const float* __restrict__ x1, const float* __restrict__ x2) {
    int b   = blockIdx.x;
    int tid = threadIdx.x;
    if (b == 0 && tid < 2*OO) {
        ((float*)g_sum)[tid]   = 0.f;
        ((float*)g_sumsq)[tid] = 0.f;
    }
    int s   = b / (NN*CC);
    int rem = b % (NN*CC);
    const float* x = s ? x2 : x1;
    const float* p = x + (size_t)rem * TTT * VV;
    float acc = 0.f;
    #pragma unroll
    for (int k = 0; k < 8; k++) acc += p[tid + k*800];
    __shared__ float part[800];
    part[tid] = acc;
    __syncthreads();
    if (tid < VV) {
        float sum = 0.f;
        #pragma unroll
        for (int tg = 0; tg < 32; tg++) sum += part[tg*VV + tid];
        g_xm[s][rem/CC][rem%CC][tid] = sum * (1.0f/TTT);
    }
}

// ---------------- K2: r = w·xm + b ------------------------------------------
__global__ void k_r(const float* __restrict__ c1w, const float* __restrict__ c1b,
                    const float* __restrict__ c2w, const float* __restrict__ c2b) {
    int i = blockIdx.x / NN, n = blockIdx.x % NN;
    int tid = threadIdx.x;
    if (tid >= 2*RR*VV) return;
    int s  = tid / (RR*VV);
    int rv = tid % (RR*VV);
    int r  = rv / VV, v = rv % VV;
    const float* w  = s ? c2w : c1w;
    const float* bb = s ? c2b : c1b;
    const float* wrow = w + (i*RR + r)*CC;
    const float* xm   = &g_xm[s][n][0][v];
    float acc = bb[i*RR + r];
    #pragma unroll 8
    for (int c = 0; c < CC; c++) acc += wrow[c] * xm[c*VV];
    g_r[s][i][n][r][v] = acc;
}

// ---------------- K3: rel=tanh(r1-r2); a1,a2 -> padded (pitch-26) g_a --------
__global__ void k_a(const float* __restrict__ PA, const float* __restrict__ alpha,
                    const float* __restrict__ c5w, const float* __restrict__ c5b,
                    const float* __restrict__ c6w, const float* __restrict__ c6b) {
    int bx = blockIdx.x;                 // o-quarter
    int i  = blockIdx.y / NN, n = blockIdx.y % NN;
    __shared__ float rel[RR][VV*VV];
    __shared__ float r1s[RR][VV], r2s[RR][VV];
    __shared__ u64  wp_s[16*RR];
    int tid = threadIdx.x;
    if (tid < RR*VV) {
        int r = tid/VV, v = tid%VV;
        r1s[r][v] = g_r[0][i][n][r][v];
        r2s[r][v] = g_r[1][i][n][r][v];
    }
    if (tid < 16*RR) {
        int o = tid / RR, r = tid % RR;
        int idx = (i*OO + bx*16 + o)*RR + r;
        wp_s[tid] = pack2(c5w[idx], c6w[idx]);
    }
    __syncthreads();
    {
        int r = 0, uv = tid;
        int u = uv / VV, v = uv - u*VV;
        while (r < RR) {
            rel[r][uv] = tanhf(r1s[r][u] - r2s[r][v]);
            uv += 256;
            if (uv >= VV*VV) { uv -= VV*VV; r++; }
            u = uv / VV; v = uv - u*VV;
        }
    }
    __syncthreads();
    float al = alpha[0];
    {
        int ol = 0, uv = tid;
        while (ol < 16) {
            int o = bx*16 + ol;
            int u = uv / VV, v = uv - u*VV;
            float a1 = c5b[i*OO + o] + PA[i*VV*VV + uv];
            float a2 = c6b[i*OO + o] + al;
            u64 acc = pack2(a1, a2);
            #pragma unroll
            for (int r = 0; r < RR; r++) {
                float rv = rel[r][uv];
                ffma2(acc, wp_s[ol*RR + r], pack2(rv, rv));
            }
            float lo, hi; unpack2(acc, lo, hi);
            g_a[0][i][n][o][u*26 + v] = lo;
            g_a[1][i][n][o][u*26 + v] = hi;
            uv += 256;
            if (uv >= VV*VV) { uv -= VV*VV; ol++; }
        }
    }
}

// ---------------- K_CONV: conv1x1 via tf32 mma.sync, fp16 x3 output ----------
// Grid (16 tv-chunks of 400, NN, 2). Block 512 = 16 warps, 2 blocks/SM.
// X staged pre-converted to tf32. A-frags shared across subsets.
// D scattered directly to pitch-26 fp16 g_x3h (STG.16; 8 consecutive-tv lanes
// per row -> contiguous 16B runs).
#define XS_PITCH  408
#define CONV_SMEM (64*XS_PITCH*4)      // 104448

__global__ void __launch_bounds__(512, 2)
k_conv(const float* __restrict__ x1, const float* __restrict__ x2,
       const float* __restrict__ c3w, const float* __restrict__ c3b,
       const float* __restrict__ c4w, const float* __restrict__ c4b) {
    extern __shared__ __align__(16) unsigned xs[];   // [64][408] tf32 bits

    int base = blockIdx.x * 400;         // tv chunk base
    int n    = blockIdx.y;
    int s    = blockIdx.z;
    const float* x  = s ? x2  : x1;
    const float* cw = s ? c4w : c3w;
    const float* cb = s ? c4b : c3b;

    int tid  = threadIdx.x;
    int wid  = tid >> 5, lane = tid & 31;
    int nt    = wid & 7;                 // o-tile (8 o)
    int mhalf = wid >> 3;
    int mtStart = mhalf ? 13 : 0;
    int mtCount = mhalf ? 12 : 13;
    int tig = lane & 3, grp = lane >> 2;
    int oc  = nt*8 + 2*tig;

    // ---- stage X chunk as tf32 bits
    for (int p4 = tid; p4 < 6400; p4 += 512) {
        int c = p4 / 100, pos = (p4 - c*100) * 4;
        float4 v = *(const float4*)(x + ((size_t)(n*CC + c))*TTT*VV + base + pos);
        uint4 u;
        u.x = to_tf32(v.x); u.y = to_tf32(v.y);
        u.z = to_tf32(v.z); u.w = to_tf32(v.w);
        *(uint4*)&xs[c*XS_PITCH + pos] = u;
    }
    __syncthreads();

    int tpad0 = (base/25)*26;            // pitch-26 output base

    // ================= pass 1: subsets 0 and 1 =================
    {
        unsigned B00[8], B01[8], B10[8], B11[8];
        #pragma unroll
        for (int k = 0; k < 8; k++) {
            B00[k] = to_tf32(cw[(0*OO + nt*8 + grp)*CC + k*8 + tig]);
            B01[k] = to_tf32(cw[(0*OO + nt*8 + grp)*CC + k*8 + tig + 4]);
            B10[k] = to_tf32(cw[(1*OO + nt*8 + grp)*CC + k*8 + tig]);
            B11[k] = to_tf32(cw[(1*OO + nt*8 + grp)*CC + k*8 + tig + 4]);
        }
        float b0lo = cb[0*OO + oc], b0hi = cb[0*OO + oc + 1];
        float b1lo = cb[1*OO + oc], b1hi = cb[1*OO + oc + 1];
        __half* dst0 = &g_x3h[s][0][n][0][0] + tpad0;
        __half* dst1 = &g_x3h[s][1][n][0][0] + tpad0;

        for (int mi = 0; mi < mtCount; mi++) {
            int m0 = (mtStart + mi) * 16;
            float d00 = b0lo, d01 = b0hi, d02 = b0lo, d03 = b0hi;
            float d10 = b1lo, d11 = b1hi, d12 = b1lo, d13 = b1hi;
            #pragma unroll
            for (int k = 0; k < 8; k++) {
                unsigned a0 = xs[(k*8 + tig    )*XS_PITCH + m0 +     grp];
                unsigned a1 = xs[(k*8 + tig    )*XS_PITCH + m0 + 8 + grp];
                unsigned a2 = xs[(k*8 + tig + 4)*XS_PITCH + m0 +     grp];
                unsigned a3 = xs[(k*8 + tig + 4)*XS_PITCH + m0 + 8 + grp];
                mma_tf32(d00, d01, d02, d03, a0, a1, a2, a3, B00[k], B01[k]);
                mma_tf32(d10, d11, d12, d13, a0, a1, a2, a3, B10[k], B11[k]);
            }
            int tv0 = m0 + grp;
            int t0 = (tv0 * 5243) >> 17; int off0 = t0*26 + (tv0 - t0*25);
            int tv1 = tv0 + 8;
            int t1 = (tv1 * 5243) >> 17; int off1 = t1*26 + (tv1 - t1*25);
            size_t r0 = (size_t)oc*X3ROW, r1 = (size_t)(oc+1)*X3ROW;
            dst0[r0 + off0] = __float2half_rn(d00);
            dst0[r1 + off0] = __float2half_rn(d01);
            dst0[r0 + off1] = __float2half_rn(d02);
            dst0[r1 + off1] = __float2half_rn(d03);
            dst1[r0 + off0] = __float2half_rn(d10);
            dst1[r1 + off0] = __float2half_rn(d11);
            dst1[r0 + off1] = __float2half_rn(d12);
            dst1[r1 + off1] = __float2half_rn(d13);
        }
    }

    // ================= pass 2: subset 2 =================
    {
        unsigned B0[8], B1[8];
        #pragma unroll
        for (int k = 0; k < 8; k++) {
            B0[k] = to_tf32(cw[(2*OO + nt*8 + grp)*CC + k*8 + tig]);
            B1[k] = to_tf32(cw[(2*OO + nt*8 + grp)*CC + k*8 + tig + 4]);
        }
        float blo = cb[2*OO + oc], bhi = cb[2*OO + oc + 1];
        __half* dst2 = &g_x3h[s][2][n][0][0] + tpad0;

        for (int mi = 0; mi < mtCount; mi++) {
            int m0 = (mtStart + mi) * 16;
            float d0 = blo, d1 = bhi, d2 = blo, d3 = bhi;
            #pragma unroll
            for (int k = 0; k < 8; k++) {
                unsigned a0 = xs[(k*8 + tig    )*XS_PITCH + m0 +     grp];
                unsigned a1 = xs[(k*8 + tig    )*XS_PITCH + m0 + 8 + grp];
                unsigned a2 = xs[(k*8 + tig + 4)*XS_PITCH + m0 +     grp];
                unsigned a3 = xs[(k*8 + tig + 4)*XS_PITCH + m0 + 8 + grp];
                mma_tf32(d0, d1, d2, d3, a0, a1, a2, a3, B0[k], B1[k]);
            }
            int tv0 = m0 + grp;
            int t0 = (tv0 * 5243) >> 17; int off0 = t0*26 + (tv0 - t0*25);
            int tv1 = tv0 + 8;
            int t1 = (tv1 * 5243) >> 17; int off1 = t1*26 + (tv1 - t1*25);
            size_t r0 = (size_t)oc*X3ROW, r1 = (size_t)(oc+1)*X3ROW;
            dst2[r0 + off0] = __float2half_rn(d0);
            dst2[r1 + off0] = __float2half_rn(d1);
            dst2[r0 + off1] = __float2half_rn(d2);
            dst2[r1 + off1] = __float2half_rn(d3);
        }
    }
}

// ---------------- K_P2: graph contraction (phase-2) --------------------------
// block = (t-tile 32, o-tile 8, (s,n)); 256 threads, 4 blocks/SM.
// x3 staged from fp16 global (uint4 = 8 halves) into fp32 pitch-26 smem rows.
#define P2_X3S  0
#define P2_AS   26624
#define P2_SMEM (26624 + 20864)

__global__ void __launch_bounds__(256, 4)
k_p2(float* __restrict__ out) {
    extern __shared__ __align__(16) char smraw[];
    float* x3s = (float*)(smraw + P2_X3S);
    float* as_ = (float*)(smraw + P2_AS);

    int tt0   = blockIdx.x * 32;
    int obase = blockIdx.y * 8;
    int z     = blockIdx.z;
    int s     = z >> 5;
    int n     = z & 31;
    float* yout = out + (size_t)s * STREAM_ELEMS;

    int tid  = threadIdx.x;
    int wid  = tid >> 5;
    int lane = tid & 31;

    float yacc[VV];
    #pragma unroll
    for (int u = 0; u < VV; u++) yacc[u] = 0.f;

    for (int i = 0; i < SS; i++) {
        __syncthreads();
        {   // x3 tile: 8 rows x 832 halves; uint4 = 8 halves -> 8 fp32
            const __half* srcb = &g_x3h[s][i][n][obase][0] + (size_t)tt0*26;
            for (int q = tid; q < 832; q += 256) {
                int ol = q / 104, j = q - ol*104;
                uint4 hv = *(const uint4*)(srcb + (size_t)ol*X3ROW + j*8);
                __half2* hp = (__half2*)&hv;
                float2 f0 = __half22float2(hp[0]);
                float2 f1 = __half22float2(hp[1]);
                float2 f2 = __half22float2(hp[2]);
                float2 f3 = __half22float2(hp[3]);
                float* d = &x3s[ol*832 + j*8];
                *(float4*)d       = make_float4(f0.x, f0.y, f1.x, f1.y);
                *(float4*)(d + 4) = make_float4(f2.x, f2.y, f3.x, f3.y);
            }
        }
        {   // a slice: 8 x 652 floats
            const float4* asrc = (const float4*)&g_a[s][i][n][obase][0];
            float4* adst = (float4*)as_;
            #pragma unroll
            for (int q = tid; q < 8*AROW/4; q += 256) adst[q] = asrc[q];
        }
        __syncthreads();

        {
            const u64* xrow = (const u64*)&x3s[wid*832 + lane*26];
            u64 xp2[12];
            #pragma unroll
            for (int j = 0; j < 12; j++) xp2[j] = xrow[j];
            float xlast = x3s[wid*832 + lane*26 + 24];
            const float* ga = &as_[wid*AROW];
            #pragma unroll
            for (int u = 0; u < VV; u++) {
                const u64* ar = (const u64*)(ga + u*26);
                u64 accA = 0ull, accB = 0ull;
                #pragma unroll
                for (int j = 0; j < 12; j += 2) {
                    ffma2(accA, ar[j],   xp2[j]);
                    ffma2(accB, ar[j+1], xp2[j+1]);
                }
                float a0, a1, b0, b1;
                unpack2(accA, a0, a1); unpack2(accB, b0, b1);
                yacc[u] += (a0 + a1) + (b0 + b1) + ga[u*26 + 24] * xlast;
            }
        }
    }

    {
        int o = obase + wid;
        float ls = 0.f, lq = 0.f;
        #pragma unroll
        for (int u = 0; u < VV; u++) { float yv = yacc[u]; ls += yv; lq += yv*yv; }
        #pragma unroll
        for (int off = 16; off; off >>= 1) {
            ls += __shfl_down_sync(0xffffffffu, ls, off);
            lq += __shfl_down_sync(0xffffffffu, lq, off);
        }
        if (lane == 0) {
            atomicAdd(&g_sum[s][o],   ls);
            atomicAdd(&g_sumsq[s][o], lq);
        }
    }

    // stage y compactly through smem, then coalesced float4 store
    __syncthreads();
    #pragma unroll
    for (int u = 0; u < VV; u++)
        x3s[wid*832 + lane*25 + u] = yacc[u];
    __syncthreads();
    {
        #pragma unroll
        for (int q = tid; q < 1600; q += 256) {
            int ol = q / 200, k4 = q - ol*200;
            float4 val = *(const float4*)&x3s[ol*832 + k4*4];
            float* dst = yout + (size_t)(n*OO + obase + ol)*TTT*VV + tt0*VV + k4*4;
            *(float4*)dst = val;
        }
    }
}

// ---------------- K5 ---------------------------------------------------------
__global__ void k_stats() {
    int i = threadIdx.x;
    if (i < 2*OO) {
        int s = i / OO, o = i % OO;
        float m = g_sum[s][o] * (1.0f/NTV);
        float v = g_sumsq[s][o] * (1.0f/NTV) - m*m;
        g_mean[s][o] = m;
        g_rstd[s][o] = rsqrtf(v + 1e-5f);
    }
}

// ---------------- K6: BN + residual + ReLU -----------------------------------
__global__ void k_bn(const float* __restrict__ x1, const float* __restrict__ x2,
                     const float* __restrict__ bn1w, const float* __restrict__ bn1b,
                     const float* __restrict__ bn2w, const float* __restrict__ bn2b,
                     float* __restrict__ out) {
    const long total4 = 2L * STREAM_ELEMS / 4;
    long stride = (long)gridDim.x * blockDim.x;
    for (long q = (long)blockIdx.x * blockDim.x + threadIdx.x; q < total4; q += stride) {
        long e   = q * 4;
        int  s   = (int)(e / STREAM_ELEMS);
        long rem = e % STREAM_ELEMS;
        int  o   = (int)((rem / (TTT*VV)) % OO);
        const float* bw = s ? bn2w : bn1w;
        const float* bb = s ? bn2b : bn1b;
        const float* xr = s ? x2   : x1;
        float m  = g_mean[s][o], rs = g_rstd[s][o];
        float sc = rs * bw[o];
        float sh = bb[o] - m * sc;
        float4 yv = ((float4*)out)[q];
        float4 xv = ((const float4*)xr)[rem/4];
        yv.x = fmaxf(fmaf(yv.x, sc, sh) + xv.x, 0.f);
        yv.y = fmaxf(fmaf(yv.y, sc, sh) + xv.y, 0.f);
        yv.z = fmaxf(fmaf(yv.z, sc, sh) + xv.z, 0.f);
        yv.w = fmaxf(fmaf(yv.w, sc, sh) + xv.w, 0.f);
        ((float4*)out)[q] = yv;
    }
}

// ---------------- launcher ---------------------------------------------------
extern "C" void kernel_launch(void* const* d_in, const int* in_sizes, int n_in,
                              void* d_out, int out_size) {
    const float* x1    = (const float*)d_in[0];
    const float* x2    = (const float*)d_in[1];
    const float* PA    = (const float*)d_in[2];
    const float* alpha = (const float*)d_in[3];
    const float* c1w   = (const float*)d_in[4];
    const float* c1b   = (const float*)d_in[5];
    const float* c2w   = (const float*)d_in[6];
    const float* c2b   = (const float*)d_in[7];
    const float* c3w   = (const float*)d_in[8];
    const float* c3b   = (const float*)d_in[9];
    const float* c4w   = (const float*)d_in[10];
    const float* c4b   = (const float*)d_in[11];
    const float* c5w   = (const float*)d_in[12];
    const float* c5b   = (const float*)d_in[13];
    const float* c6w   = (const float*)d_in[14];
    const float* c6b   = (const float*)d_in[15];
    const float* bn1w  = (const float*)d_in[16];
    const float* bn1b  = (const float*)d_in[17];
    const float* bn2w  = (const float*)d_in[18];
    const float* bn2b  = (const float*)d_in[19];
    float* out = (float*)d_out;

    cudaFuncSetAttribute(k_conv, cudaFuncAttributeMaxDynamicSharedMemorySize, CONV_SMEM);
    cudaFuncSetAttribute(k_p2,   cudaFuncAttributeMaxDynamicSharedMemorySize, P2_SMEM);

    k_mean<<<2*NN*CC, 800>>>(x1, x2);
    k_r<<<SS*NN, 512>>>(c1w, c1b, c2w, c2b);
    k_a<<<dim3(4, SS*NN), 256>>>(PA, alpha, c5w, c5b, c6w, c6b);
    k_conv<<<dim3(16, NN, 2), 512, CONV_SMEM>>>(x1, x2, c3w, c3b, c4w, c4b);
    k_p2<<<dim3(TTT/32, OO/8, 2*NN), 256, P2_SMEM>>>(out);
    k_stats<<<1, 128>>>();
    k_bn<<<8192, 256>>>(x1, x2, bn1w, bn1b, bn2w, bn2b, out);
}

// round 17
// speedup vs baseline: 1.9533x; 1.1006x over previous
#include <cuda_runtime.h>
#include <cuda_fp16.h>

// Problem constants
#define NN 32
#define CC 64
#define TTT 256
#define VV 25
#define RR 8
#define OO 64
#define SS 3
#define STREAM_ELEMS (NN*OO*TTT*VV)   // 13,107,200
#define NTV (NN*TTT*VV)               // 204,800
#define X3ROW 8192                    // per-o x3 row: 256 t * 32 (halves)
#define AHROW 1000                    // per-o fp16 a block in global: 25 u * 40
#define ASTRIDE 1280                  // per-(i,o) a block in smem: 32 u * 40

typedef unsigned long long u64;

__device__ __forceinline__ u64 pack2(float lo, float hi) {
    u64 r; asm("mov.b64 %0,{%1,%2};" : "=l"(r) : "f"(lo), "f"(hi)); return r;
}
__device__ __forceinline__ void unpack2(u64 p, float& lo, float& hi) {
    asm("mov.b64 {%0,%1},%2;" : "=f"(lo), "=f"(hi) : "l"(p));
}
__device__ __forceinline__ void ffma2(u64& d, u64 a, u64 b) {
    asm("fma.rn.f32x2 %0,%1,%2,%0;" : "+l"(d) : "l"(a), "l"(b));
}
__device__ __forceinline__ unsigned to_tf32(float f) {
    unsigned r; asm("cvt.rna.tf32.f32 %0, %1;" : "=r"(r) : "f"(f)); return r;
}
__device__ __forceinline__ void mma_tf32(float& d0, float& d1, float& d2, float& d3,
                                         unsigned a0, unsigned a1, unsigned a2, unsigned a3,
                                         unsigned b0, unsigned b1) {
    asm volatile(
        "mma.sync.aligned.m16n8k8.row.col.f32.tf32.tf32.f32 "
        "{%0,%1,%2,%3},{%4,%5,%6,%7},{%8,%9},{%0,%1,%2,%3};\n"
        : "+f"(d0), "+f"(d1), "+f"(d2), "+f"(d3)
        : "r"(a0), "r"(a1), "r"(a2), "r"(a3), "r"(b0), "r"(b1));
}
__device__ __forceinline__ void mma_f16(float& d0, float& d1, float& d2, float& d3,
                                        unsigned a0, unsigned a1, unsigned a2, unsigned a3,
                                        unsigned b0, unsigned b1) {
    asm volatile(
        "mma.sync.aligned.m16n8k16.row.col.f32.f16.f16.f32 "
        "{%0,%1,%2,%3},{%4,%5,%6,%7},{%8,%9},{%0,%1,%2,%3};\n"
        : "+f"(d0), "+f"(d1), "+f"(d2), "+f"(d3)
        : "r"(a0), "r"(a1), "r"(a2), "r"(a3), "r"(b0), "r"(b1));
}

// ---------------- scratch (zero-init; pads never written -> stay 0) ----------
__device__ float  g_xm[2][NN][CC][VV];
__device__ float  g_r[2][SS][NN][RR][VV];
__device__ __half g_ah[2][SS][NN][OO][AHROW];       // fp16 a, pitch-40 u-rows
__device__ __half g_x3h[2][SS][NN][OO][X3ROW];      // fp16 conv out, pitch-32
__device__ float  g_sum[2][OO];
__device__ float  g_sumsq[2][OO];
__device__ float  g_mean[2][OO];
__device__ float  g_rstd[2][OO];

// ---------------- K1: mean over T (+ zero stats in block 0) ------------------
__global__ void k_mean(const float* __restrict__ x1, const float* __restrict__ x2) {
    int b   = blockIdx.x;
    int tid = threadIdx.x;
    if (b == 0 && tid < 2*OO) {
        ((float*)g_sum)[tid]   = 0.f;
        ((float*)g_sumsq)[tid] = 0.f;
    }
    int s   = b / (NN*CC);
    int rem = b % (NN*CC);
    const float* x = s ? x2 : x1;
    const float* p = x + (size_t)rem * TTT * VV;
    float acc = 0.f;
    #pragma unroll
    for (int k = 0; k < 8; k++) acc += p[tid + k*800];
    __shared__ float part[800];
    part[tid] = acc;
    __syncthreads();
    if (tid < VV) {
        float sum = 0.f;
        #pragma unroll
        for (int tg = 0; tg < 32; tg++) sum += part[tg*VV + tid];
        g_xm[s][rem/CC][rem%CC][tid] = sum * (1.0f/TTT);
    }
}

// ---------------- K2: r = w·xm + b ------------------------------------------
__global__ void k_r(const float* __restrict__ c1w, const float* __restrict__ c1b,
                    const float* __restrict__ c2w, const float* __restrict__ c2b) {
    int i = blockIdx.x / NN, n = blockIdx.x % NN;
    int tid = threadIdx.x;
    if (tid >= 2*RR*VV) return;
    int s  = tid / (RR*VV);
    int rv = tid % (RR*VV);
    int r  = rv / VV, v = rv % VV;
    const float* w  = s ? c2w : c1w;
    const float* bb = s ? c2b : c1b;
    const float* wrow = w + (i*RR + r)*CC;
    const float* xm   = &g_xm[s][n][0][v];
    float acc = bb[i*RR + r];
    #pragma unroll 8
    for (int c = 0; c < CC; c++) acc += wrow[c] * xm[c*VV];
    g_r[s][i][n][r][v] = acc;
}

// ---------------- K3: rel=tanh(r1-r2); a1,a2 -> fp16 pitch-40 g_ah -----------
__global__ void k_a(const float* __restrict__ PA, const float* __restrict__ alpha,
                    const float* __restrict__ c5w, const float* __restrict__ c5b,
                    const float* __restrict__ c6w, const float* __restrict__ c6b) {
    int bx = blockIdx.x;                 // o-quarter
    int i  = blockIdx.y / NN, n = blockIdx.y % NN;
    __shared__ float rel[RR][VV*VV];
    __shared__ float r1s[RR][VV], r2s[RR][VV];
    __shared__ u64  wp_s[16*RR];
    int tid = threadIdx.x;
    if (tid < RR*VV) {
        int r = tid/VV, v = tid%VV;
        r1s[r][v] = g_r[0][i][n][r][v];
        r2s[r][v] = g_r[1][i][n][r][v];
    }
    if (tid < 16*RR) {
        int o = tid / RR, r = tid % RR;
        int idx = (i*OO + bx*16 + o)*RR + r;
        wp_s[tid] = pack2(c5w[idx], c6w[idx]);
    }
    __syncthreads();
    {
        int r = 0, uv = tid;
        int u = uv / VV, v = uv - u*VV;
        while (r < RR) {
            rel[r][uv] = tanhf(r1s[r][u] - r2s[r][v]);
            uv += 256;
            if (uv >= VV*VV) { uv -= VV*VV; r++; }
            u = uv / VV; v = uv - u*VV;
        }
    }
    __syncthreads();
    float al = alpha[0];
    {
        int ol = 0, uv = tid;
        while (ol < 16) {
            int o = bx*16 + ol;
            int u = uv / VV, v = uv - u*VV;
            float a1 = c5b[i*OO + o] + PA[i*VV*VV + uv];
            float a2 = c6b[i*OO + o] + al;
            u64 acc = pack2(a1, a2);
            #pragma unroll
            for (int r = 0; r < RR; r++) {
                float rv = rel[r][uv];
                ffma2(acc, wp_s[ol*RR + r], pack2(rv, rv));
            }
            float lo, hi; unpack2(acc, lo, hi);
            g_ah[0][i][n][o][u*40 + v] = __float2half_rn(lo);
            g_ah[1][i][n][o][u*40 + v] = __float2half_rn(hi);
            uv += 256;
            if (uv >= VV*VV) { uv -= VV*VV; ol++; }
        }
    }
}

// ---------------- K_CONV: conv1x1 via tf32 mma.sync, fp16 pitch-32 out -------
#define XS_PITCH  408
#define CONV_SMEM (64*XS_PITCH*4)      // 104448

__global__ void __launch_bounds__(512, 2)
k_conv(const float* __restrict__ x1, const float* __restrict__ x2,
       const float* __restrict__ c3w, const float* __restrict__ c3b,
       const float* __restrict__ c4w, const float* __restrict__ c4b) {
    extern __shared__ __align__(16) unsigned xs[];   // [64][408] tf32 bits

    int base = blockIdx.x * 400;         // tv chunk base
    int n    = blockIdx.y;
    int s    = blockIdx.z;
    const float* x  = s ? x2  : x1;
    const float* cw = s ? c4w : c3w;
    const float* cb = s ? c4b : c3b;

    int tid  = threadIdx.x;
    int wid  = tid >> 5, lane = tid & 31;
    int nt    = wid & 7;                 // o-tile (8 o)
    int mhalf = wid >> 3;
    int mtStart = mhalf ? 13 : 0;
    int mtCount = mhalf ? 12 : 13;
    int tig = lane & 3, grp = lane >> 2;
    int oc  = nt*8 + 2*tig;

    // ---- stage X chunk as tf32 bits
    for (int p4 = tid; p4 < 6400; p4 += 512) {
        int c = p4 / 100, pos = (p4 - c*100) * 4;
        float4 v = *(const float4*)(x + ((size_t)(n*CC + c))*TTT*VV + base + pos);
        uint4 u;
        u.x = to_tf32(v.x); u.y = to_tf32(v.y);
        u.z = to_tf32(v.z); u.w = to_tf32(v.w);
        *(uint4*)&xs[c*XS_PITCH + pos] = u;
    }
    __syncthreads();

    int tpad0 = (base/25)*32;            // pitch-32 output base

    // ================= pass 1: subsets 0 and 1 =================
    {
        unsigned B00[8], B01[8], B10[8], B11[8];
        #pragma unroll
        for (int k = 0; k < 8; k++) {
            B00[k] = to_tf32(cw[(0*OO + nt*8 + grp)*CC + k*8 + tig]);
            B01[k] = to_tf32(cw[(0*OO + nt*8 + grp)*CC + k*8 + tig + 4]);
            B10[k] = to_tf32(cw[(1*OO + nt*8 + grp)*CC + k*8 + tig]);
            B11[k] = to_tf32(cw[(1*OO + nt*8 + grp)*CC + k*8 + tig + 4]);
        }
        float b0lo = cb[0*OO + oc], b0hi = cb[0*OO + oc + 1];
        float b1lo = cb[1*OO + oc], b1hi = cb[1*OO + oc + 1];
        __half* dst0 = &g_x3h[s][0][n][0][0] + tpad0;
        __half* dst1 = &g_x3h[s][1][n][0][0] + tpad0;

        for (int mi = 0; mi < mtCount; mi++) {
            int m0 = (mtStart + mi) * 16;
            float d00 = b0lo, d01 = b0hi, d02 = b0lo, d03 = b0hi;
            float d10 = b1lo, d11 = b1hi, d12 = b1lo, d13 = b1hi;
            #pragma unroll
            for (int k = 0; k < 8; k++) {
                unsigned a0 = xs[(k*8 + tig    )*XS_PITCH + m0 +     grp];
                unsigned a1 = xs[(k*8 + tig    )*XS_PITCH + m0 + 8 + grp];
                unsigned a2 = xs[(k*8 + tig + 4)*XS_PITCH + m0 +     grp];
                unsigned a3 = xs[(k*8 + tig + 4)*XS_PITCH + m0 + 8 + grp];
                mma_tf32(d00, d01, d02, d03, a0, a1, a2, a3, B00[k], B01[k]);
                mma_tf32(d10, d11, d12, d13, a0, a1, a2, a3, B10[k], B11[k]);
            }
            int tv0 = m0 + grp;
            int t0 = (tv0 * 5243) >> 17; int off0 = t0*32 + (tv0 - t0*25);
            int tv1 = tv0 + 8;
            int t1 = (tv1 * 5243) >> 17; int off1 = t1*32 + (tv1 - t1*25);
            size_t r0 = (size_t)oc*X3ROW, r1 = (size_t)(oc+1)*X3ROW;
            dst0[r0 + off0] = __float2half_rn(d00);
            dst0[r1 + off0] = __float2half_rn(d01);
            dst0[r0 + off1] = __float2half_rn(d02);
            dst0[r1 + off1] = __float2half_rn(d03);
            dst1[r0 + off0] = __float2half_rn(d10);
            dst1[r1 + off0] = __float2half_rn(d11);
            dst1[r0 + off1] = __float2half_rn(d12);
            dst1[r1 + off1] = __float2half_rn(d13);
        }
    }

    // ================= pass 2: subset 2 =================
    {
        unsigned B0[8], B1[8];
        #pragma unroll
        for (int k = 0; k < 8; k++) {
            B0[k] = to_tf32(cw[(2*OO + nt*8 + grp)*CC + k*8 + tig]);
            B1[k] = to_tf32(cw[(2*OO + nt*8 + grp)*CC + k*8 + tig + 4]);
        }
        float blo = cb[2*OO + oc], bhi = cb[2*OO + oc + 1];
        __half* dst2 = &g_x3h[s][2][n][0][0] + tpad0;

        for (int mi = 0; mi < mtCount; mi++) {
            int m0 = (mtStart + mi) * 16;
            float d0 = blo, d1 = bhi, d2 = blo, d3 = bhi;
            #pragma unroll
            for (int k = 0; k < 8; k++) {
                unsigned a0 = xs[(k*8 + tig    )*XS_PITCH + m0 +     grp];
                unsigned a1 = xs[(k*8 + tig    )*XS_PITCH + m0 + 8 + grp];
                unsigned a2 = xs[(k*8 + tig + 4)*XS_PITCH + m0 +     grp];
                unsigned a3 = xs[(k*8 + tig + 4)*XS_PITCH + m0 + 8 + grp];
                mma_tf32(d0, d1, d2, d3, a0, a1, a2, a3, B0[k], B1[k]);
            }
            int tv0 = m0 + grp;
            int t0 = (tv0 * 5243) >> 17; int off0 = t0*32 + (tv0 - t0*25);
            int tv1 = tv0 + 8;
            int t1 = (tv1 * 5243) >> 17; int off1 = t1*32 + (tv1 - t1*25);
            size_t r0 = (size_t)oc*X3ROW, r1 = (size_t)(oc+1)*X3ROW;
            dst2[r0 + off0] = __float2half_rn(d0);
            dst2[r1 + off0] = __float2half_rn(d1);
            dst2[r0 + off1] = __float2half_rn(d2);
            dst2[r1 + off1] = __float2half_rn(d3);
        }
    }
}

// ---------------- K_P2: phase-2 via fp16 mma ---------------------------------
// block = (t-tile 64, o-tile 8, (s,n)); 256 thr = 8 warps; warp = one o.
// smem: x3s [8o][64t][40v] halves (40960B) + ash [24][1280] halves (61440B).
// ash stride 1280 (32 u-rows): u=25..31 B-frag reads land on zero-filled rows.
#define P2_X3H  0
#define P2_ASH  20480                  // halves offset of ash
#define P2_SMEM ((20480 + 24*ASTRIDE)*2)   // 102400 bytes

__global__ void __launch_bounds__(256, 2)
k_p2(float* __restrict__ out) {
    extern __shared__ __align__(16) __half p2s[];
    __half* x3s = p2s + P2_X3H;
    __half* ash = p2s + P2_ASH;

    int tt0   = blockIdx.x * 64;
    int obase = blockIdx.y * 8;
    int z     = blockIdx.z;
    int s     = z >> 5;
    int n     = z & 31;
    float* yout = out + (size_t)s * STREAM_ELEMS;

    int tid  = threadIdx.x;
    int wid  = tid >> 5, lane = tid & 31;
    int grp  = lane >> 2, tig = lane & 3;
    int o    = wid;                      // warp -> o in tile

    // zero ALL smem (x3s pads v32..39 and ash rows u25..31 must be 0)
    for (int q = tid; q < (20480 + 24*ASTRIDE)/8; q += 256)
        ((uint4*)p2s)[q] = make_uint4(0,0,0,0);
    __syncthreads();
    // stage fp16 a: 3 subsets x 8 o x 125 uint4 (into stride-1280 blocks)
    for (int q = tid; q < 3000; q += 256) {
        int io = q / 125, j = q - io*125;
        int i  = io >> 3, ol = io & 7;
        ((uint4*)(ash + io*ASTRIDE))[j] =
            ((const uint4*)&g_ah[s][i][n][obase + ol][0])[j];
    }

    float D[4][4][4];
    #pragma unroll
    for (int mt = 0; mt < 4; mt++)
        #pragma unroll
        for (int ntt = 0; ntt < 4; ntt++)
            #pragma unroll
            for (int r = 0; r < 4; r++) D[mt][ntt][r] = 0.f;

    for (int i = 0; i < SS; i++) {
        __syncthreads();   // a/zero-stage done (i=0) / prior mma reads done
        // stage x3: 8o x 64t x 4 uint4 (32 halves per t-row)
        for (int q = tid; q < 2048; q += 256) {
            int o2 = q >> 8, rem = q & 255;
            int t = rem >> 2, j = rem & 3;
            uint4 v = *(const uint4*)(&g_x3h[s][i][n][obase + o2][0]
                                      + (size_t)(tt0 + t)*32 + j*8);
            *(uint4*)&x3s[(o2*64 + t)*40 + j*8] = v;
        }
        __syncthreads();

        // B-frags for this (i, o): a[u][v]; rows u>=25 are zeros
        const __half* ab = &ash[(i*8 + o)*ASTRIDE];
        unsigned Bf[4][2][2];
        #pragma unroll
        for (int ntt = 0; ntt < 4; ntt++)
            #pragma unroll
            for (int ks = 0; ks < 2; ks++) {
                int ubase = (ntt*8 + grp)*40 + ks*16 + 2*tig;
                Bf[ntt][ks][0] = *(const unsigned*)&ab[ubase];
                Bf[ntt][ks][1] = *(const unsigned*)&ab[ubase + 8];
            }

        const __half* xb = &x3s[o*64*40];
        #pragma unroll
        for (int mt = 0; mt < 4; mt++) {
            int rbase = (mt*16 + grp)*40;
            #pragma unroll
            for (int ks = 0; ks < 2; ks++) {
                int kofs = ks*16 + 2*tig;
                unsigned a0 = *(const unsigned*)&xb[rbase + kofs];
                unsigned a1 = *(const unsigned*)&xb[rbase + 8*40 + kofs];
                unsigned a2 = *(const unsigned*)&xb[rbase + kofs + 8];
                unsigned a3 = *(const unsigned*)&xb[rbase + 8*40 + kofs + 8];
                #pragma unroll
                for (int ntt = 0; ntt < 4; ntt++)
                    mma_f16(D[mt][ntt][0], D[mt][ntt][1], D[mt][ntt][2], D[mt][ntt][3],
                            a0, a1, a2, a3, Bf[ntt][ks][0], Bf[ntt][ks][1]);
            }
        }
    }

    // ---- epilogue: stats + y store from D regs
    float ls = 0.f, lq = 0.f;
    float* yo = yout + (size_t)(n*OO + obase + o)*TTT*VV;
    #pragma unroll
    for (int mt = 0; mt < 4; mt++) {
        int row0 = tt0 + mt*16 + grp;
        #pragma unroll
        for (int ntt = 0; ntt < 4; ntt++) {
            int u0 = ntt*8 + 2*tig;
            #pragma unroll
            for (int r = 0; r < 4; r++) {
                int u = u0 + (r & 1);
                int t = row0 + ((r & 2) ? 8 : 0);
                float val = D[mt][ntt][r];
                if (u < VV) {
                    yo[t*VV + u] = val;
                    ls += val; lq += val*val;
                }
            }
        }
    }
    #pragma unroll
    for (int off = 16; off; off >>= 1) {
        ls += __shfl_down_sync(0xffffffffu, ls, off);
        lq += __shfl_down_sync(0xffffffffu, lq, off);
    }
    if (lane == 0) {
        atomicAdd(&g_sum[s][obase + o],   ls);
        atomicAdd(&g_sumsq[s][obase + o], lq);
    }
}

// ---------------- K5 ---------------------------------------------------------
__global__ void k_stats() {
    int i = threadIdx.x;
    if (i < 2*OO) {
        int s = i / OO, o = i % OO;
        float m = g_sum[s][o] * (1.0f/NTV);
        float v = g_sumsq[s][o] * (1.0f/NTV) - m*m;
        g_mean[s][o] = m;
        g_rstd[s][o] = rsqrtf(v + 1e-5f);
    }
}

// ---------------- K6: BN + residual + ReLU -----------------------------------
__global__ void k_bn(const float* __restrict__ x1, const float* __restrict__ x2,
                     const float* __restrict__ bn1w, const float* __restrict__ bn1b,
                     const float* __restrict__ bn2w, const float* __restrict__ bn2b,
                     float* __restrict__ out) {
    const long total4 = 2L * STREAM_ELEMS / 4;
    long stride = (long)gridDim.x * blockDim.x;
    for (long q = (long)blockIdx.x * blockDim.x + threadIdx.x; q < total4; q += stride) {
        long e   = q * 4;
        int  s   = (int)(e / STREAM_ELEMS);
        long rem = e % STREAM_ELEMS;
        int  o   = (int)((rem / (TTT*VV)) % OO);
        const float* bw = s ? bn2w : bn1w;
        const float* bb = s ? bn2b : bn1b;
        const float* xr = s ? x2   : x1;
        float m  = g_mean[s][o], rs = g_rstd[s][o];
        float sc = rs * bw[o];
        float sh = bb[o] - m * sc;
        float4 yv = ((float4*)out)[q];
        float4 xv = ((const float4*)xr)[rem/4];
        yv.x = fmaxf(fmaf(yv.x, sc, sh) + xv.x, 0.f);
        yv.y = fmaxf(fmaf(yv.y, sc, sh) + xv.y, 0.f);
        yv.z = fmaxf(fmaf(yv.z, sc, sh) + xv.z, 0.f);
        yv.w = fmaxf(fmaf(yv.w, sc, sh) + xv.w, 0.f);
        ((float4*)out)[q] = yv;
    }
}

// ---------------- launcher ---------------------------------------------------
extern "C" void kernel_launch(void* const* d_in, const int* in_sizes, int n_in,
                              void* d_out, int out_size) {
    const float* x1    = (const float*)d_in[0];
    const float* x2    = (const float*)d_in[1];
    const float* PA    = (const float*)d_in[2];
    const float* alpha = (const float*)d_in[3];
    const float* c1w   = (const float*)d_in[4];
    const float* c1b   = (const float*)d_in[5];
    const float* c2w   = (const float*)d_in[6];
    const float* c2b   = (const float*)d_in[7];
    const float* c3w   = (const float*)d_in[8];
    const float* c3b   = (const float*)d_in[9];
    const float* c4w   = (const float*)d_in[10];
    const float* c4b   = (const float*)d_in[11];
    const float* c5w   = (const float*)d_in[12];
    const float* c5b   = (const float*)d_in[13];
    const float* c6w   = (const float*)d_in[14];
    const float* c6b   = (const float*)d_in[15];
    const float* bn1w  = (const float*)d_in[16];
    const float* bn1b  = (const float*)d_in[17];
    const float* bn2w  = (const float*)d_in[18];
    const float* bn2b  = (const float*)d_in[19];
    float* out = (float*)d_out;

    cudaFuncSetAttribute(k_conv, cudaFuncAttributeMaxDynamicSharedMemorySize, CONV_SMEM);
    cudaFuncSetAttribute(k_p2,   cudaFuncAttributeMaxDynamicSharedMemorySize, P2_SMEM);

    k_mean<<<2*NN*CC, 800>>>(x1, x2);
    k_r<<<SS*NN, 512>>>(c1w, c1b, c2w, c2b);
    k_a<<<dim3(4, SS*NN), 256>>>(PA, alpha, c5w, c5b, c6w, c6b);
    k_conv<<<dim3(16, NN, 2), 512, CONV_SMEM>>>(x1, x2, c3w, c3b, c4w, c4b);
    k_p2<<<dim3(TTT/64, OO/8, 2*NN), 256, P2_SMEM>>>(out);
    k_stats<<<1, 128>>>();
    k_bn<<<8192, 256>>>(x1, x2, bn1w, bn1b, bn2w, bn2b, out);
}